// round 1
// baseline (speedup 1.0000x reference)
#include <cuda_runtime.h>
#include <math.h>

#define NN 100000
#define NE 1600000
#define F  128

// Scratch (allocation-free rule: __device__ globals)
__device__ float g_h[(size_t)NN * F];    // 51.2 MB
__device__ float g_agg[(size_t)NN * F];  // 51.2 MB
__device__ float g_deg[NN];

// ---------------- zeroing ----------------
__global__ void k_zero_scratch() {
  size_t i = (size_t)blockIdx.x * blockDim.x + threadIdx.x;
  if (i < (size_t)NN * F) g_agg[i] = 0.0f;
  if (i < NN) g_deg[i] = 0.0f;
}

__global__ void k_zero_buf(float* __restrict__ p) {
  size_t i = (size_t)blockIdx.x * blockDim.x + threadIdx.x;
  if (i < (size_t)NN * F) p[i] = 0.0f;
}

// ---------------- degree ----------------
__global__ void k_deg(const int* __restrict__ row) {
  int e = blockIdx.x * blockDim.x + threadIdx.x;
  if (e < NE) atomicAdd(&g_deg[row[e]], 1.0f);
}

// ---------------- GEMM: C[m][n] = sum_k A[m][k] * W[n][k] + b[n] ----------------
// K = N = 128. Block tile: 64 (M) x 128 (N), K-tile 32. 256 threads,
// per-thread microtile 8(M) x 4(N).
__global__ __launch_bounds__(256) void k_gemm_bias(
    const float* __restrict__ A, const float* __restrict__ W,
    const float* __restrict__ bias, float* __restrict__ C, int M) {
  __shared__ float sA[64][36];    // +4 pad keeps float4 alignment (36*4=144, %16==0)
  __shared__ float sB[32][128];   // transposed W tile: sB[k][n]

  const int tid = threadIdx.x;
  const int tx = tid & 31;        // n-quad: columns tx*4 .. tx*4+3
  const int ty = tid >> 5;        // m-group: rows ty*8 .. ty*8+7
  const int m0 = blockIdx.x * 64;

  float acc[8][4];
#pragma unroll
  for (int i = 0; i < 8; i++)
#pragma unroll
    for (int j = 0; j < 4; j++) acc[i][j] = 0.0f;

  for (int k0 = 0; k0 < 128; k0 += 32) {
    // Load A tile 64x32 (512 float4, 2 per thread)
#pragma unroll
    for (int l = 0; l < 2; l++) {
      int idx = tid + l * 256;
      int m = idx >> 3;
      int kq = idx & 7;
      float4 v = make_float4(0.f, 0.f, 0.f, 0.f);
      if (m0 + m < M)
        v = *(const float4*)(A + (size_t)(m0 + m) * F + k0 + kq * 4);
      *(float4*)&sA[m][kq * 4] = v;
    }
    // Load W tile 128x32, transposed into sB[k][n] (1024 float4, 4 per thread)
#pragma unroll
    for (int l = 0; l < 4; l++) {
      int idx = tid + l * 256;
      int n = idx >> 3;
      int kq = idx & 7;
      float4 v = *(const float4*)(W + (size_t)n * F + k0 + kq * 4);
      sB[kq * 4 + 0][n] = v.x;
      sB[kq * 4 + 1][n] = v.y;
      sB[kq * 4 + 2][n] = v.z;
      sB[kq * 4 + 3][n] = v.w;
    }
    __syncthreads();

#pragma unroll
    for (int kk = 0; kk < 32; kk++) {
      float b[4];
      *(float4*)b = *(const float4*)&sB[kk][tx * 4];   // conflict-free (16B stride)
#pragma unroll
      for (int i = 0; i < 8; i++) {
        float a = sA[ty * 8 + i][kk];                  // warp-broadcast
        acc[i][0] += a * b[0];
        acc[i][1] += a * b[1];
        acc[i][2] += a * b[2];
        acc[i][3] += a * b[3];
      }
    }
    __syncthreads();
  }

  float4 bb = *(const float4*)(bias + tx * 4);
#pragma unroll
  for (int i = 0; i < 8; i++) {
    int m = m0 + ty * 8 + i;
    if (m < M) {
      float4 o;
      o.x = acc[i][0] + bb.x;
      o.y = acc[i][1] + bb.y;
      o.z = acc[i][2] + bb.z;
      o.w = acc[i][3] + bb.w;
      *(float4*)(C + (size_t)m * F + tx * 4) = o;
    }
  }
}

// ---------------- scatter-add SpMM: dst[row[e]] += src[col[e]] ----------------
// One warp per edge; lane handles a float4 (4 features). Warp reads the full
// 512B source row coalesced; atomics spread across 100k*128 addresses.
__global__ __launch_bounds__(256) void k_scatter(
    const float* __restrict__ src, float* __restrict__ dst,
    const int* __restrict__ row, const int* __restrict__ col) {
  int warp = (blockIdx.x * 256 + threadIdx.x) >> 5;
  if (warp >= NE) return;
  int lane = threadIdx.x & 31;
  int c = __ldg(col + warp);
  int r = __ldg(row + warp);
  float4 v = ((const float4*)(src + (size_t)c * F))[lane];
  float* d = dst + (size_t)r * F + lane * 4;
  atomicAdd(d + 0, v.x);
  atomicAdd(d + 1, v.y);
  atomicAdd(d + 2, v.z);
  atomicAdd(d + 3, v.w);
}

// ---------------- scale by 1/deg, optional ELU ----------------
__global__ void k_post(float* __restrict__ data, int apply_elu) {
  size_t i = (size_t)blockIdx.x * blockDim.x + threadIdx.x;
  if (i >= (size_t)NN * F) return;
  int node = (int)(i >> 7);
  float d = g_deg[node];
  float inv = d > 0.0f ? 1.0f / d : 0.0f;
  float v = data[i] * inv;
  if (apply_elu) v = v > 0.0f ? v : expm1f(v);
  data[i] = v;
}

extern "C" void kernel_launch(void* const* d_in, const int* in_sizes, int n_in,
                              void* d_out, int out_size) {
  const float* x  = (const float*)d_in[0];
  const int*   ei = (const int*)d_in[1];
  const float* W1 = (const float*)d_in[2];
  const float* b1 = (const float*)d_in[3];
  const float* W2 = (const float*)d_in[4];
  const float* b2 = (const float*)d_in[5];
  const int* row = ei;
  const int* col = ei + NE;
  float* out = (float*)d_out;

  void* p_h = nullptr;
  void* p_agg = nullptr;
  cudaGetSymbolAddress(&p_h, g_h);
  cudaGetSymbolAddress(&p_agg, g_agg);
  float* h   = (float*)p_h;
  float* agg = (float*)p_agg;

  const size_t total = (size_t)NN * F;          // 12.8M
  const int elem_blocks = (int)((total + 255) / 256);

  k_zero_scratch<<<elem_blocks, 256>>>();                       // agg=0, deg=0
  k_deg<<<(NE + 255) / 256, 256>>>(row);                        // degree
  k_gemm_bias<<<(NN + 63) / 64, 256>>>(x, W1, b1, h, NN);       // h = x W1^T + b1
  k_scatter<<<NE / 8, 256>>>(h, agg, row, col);                 // agg = A h
  k_post<<<elem_blocks, 256>>>(agg, 1);                         // agg = elu(agg/deg)
  k_gemm_bias<<<(NN + 63) / 64, 256>>>(agg, W2, b2, h, NN);     // h = agg W2^T + b2
  k_zero_buf<<<elem_blocks, 256>>>(out);                        // out = 0
  k_scatter<<<NE / 8, 256>>>(h, out, row, col);                 // out = A h
  k_post<<<elem_blocks, 256>>>(out, 0);                         // out /= deg
}

// round 2
// speedup vs baseline: 3.4481x; 3.4481x over previous
#include <cuda_runtime.h>
#include <math.h>

#define NN 100000
#define NE 1600000
#define F  128
#define SCAN_B 512
#define NBLK ((NN + SCAN_B - 1) / SCAN_B)   // 196

// Scratch (allocation-free rule: __device__ globals)
__device__ float g_h[(size_t)NN * F];      // 51.2 MB
__device__ float g_agg[(size_t)NN * F];    // 51.2 MB
__device__ int   g_cnt[NN];                // histogram, then placement cursor
__device__ int   g_rptr[NN + 1];           // CSR row pointers
__device__ int   g_scol[NE];               // CSR column indices (sorted by row)
__device__ int   g_part[SCAN_B];           // block partial sums for scan

// ---------------- CSR build ----------------
__global__ void k_zero_cnt() {
  int i = blockIdx.x * blockDim.x + threadIdx.x;
  if (i < NN) g_cnt[i] = 0;
}

__global__ void k_hist(const int* __restrict__ row) {
  int e = blockIdx.x * blockDim.x + threadIdx.x;
  if (e < NE) atomicAdd(&g_cnt[row[e]], 1);
}

// Block-local exclusive scan of counts -> rptr, block totals -> part
__global__ __launch_bounds__(SCAN_B) void k_scanA() {
  __shared__ int sh[SCAN_B];
  int g = blockIdx.x * SCAN_B + threadIdx.x;
  int v = (g < NN) ? g_cnt[g] : 0;
  sh[threadIdx.x] = v;
  __syncthreads();
#pragma unroll
  for (int off = 1; off < SCAN_B; off <<= 1) {
    int t = (threadIdx.x >= off) ? sh[threadIdx.x - off] : 0;
    __syncthreads();
    sh[threadIdx.x] += t;
    __syncthreads();
  }
  if (g < NN) g_rptr[g] = sh[threadIdx.x] - v;     // exclusive within block
  if (threadIdx.x == SCAN_B - 1) g_part[blockIdx.x] = sh[SCAN_B - 1];
}

// Single-block exclusive scan of the NBLK partials
__global__ __launch_bounds__(SCAN_B) void k_scanB() {
  __shared__ int sh[SCAN_B];
  int v = (threadIdx.x < NBLK) ? g_part[threadIdx.x] : 0;
  sh[threadIdx.x] = v;
  __syncthreads();
#pragma unroll
  for (int off = 1; off < SCAN_B; off <<= 1) {
    int t = (threadIdx.x >= off) ? sh[threadIdx.x - off] : 0;
    __syncthreads();
    sh[threadIdx.x] += t;
    __syncthreads();
  }
  g_part[threadIdx.x] = sh[threadIdx.x] - v;       // exclusive
}

// Add block offsets; reset cursor; set sentinel
__global__ __launch_bounds__(SCAN_B) void k_scanC() {
  int g = blockIdx.x * SCAN_B + threadIdx.x;
  if (g < NN) {
    g_rptr[g] += g_part[blockIdx.x];
    g_cnt[g] = 0;                                   // reuse as placement cursor
  }
  if (g == 0) g_rptr[NN] = NE;
}

__global__ void k_place(const int* __restrict__ row, const int* __restrict__ col) {
  int e = blockIdx.x * blockDim.x + threadIdx.x;
  if (e >= NE) return;
  int r = row[e];
  int pos = g_rptr[r] + atomicAdd(&g_cnt[r], 1);
  g_scol[pos] = col[e];
}

// ---------------- GEMM: C[m][n] = sum_k A[m][k] * W[n][k] + b[n] ----------------
__global__ __launch_bounds__(256) void k_gemm_bias(
    const float* __restrict__ A, const float* __restrict__ W,
    const float* __restrict__ bias, float* __restrict__ C, int M) {
  __shared__ float sA[64][36];
  __shared__ float sB[32][128];

  const int tid = threadIdx.x;
  const int tx = tid & 31;
  const int ty = tid >> 5;
  const int m0 = blockIdx.x * 64;

  float acc[8][4];
#pragma unroll
  for (int i = 0; i < 8; i++)
#pragma unroll
    for (int j = 0; j < 4; j++) acc[i][j] = 0.0f;

  for (int k0 = 0; k0 < 128; k0 += 32) {
#pragma unroll
    for (int l = 0; l < 2; l++) {
      int idx = tid + l * 256;
      int m = idx >> 3;
      int kq = idx & 7;
      float4 v = make_float4(0.f, 0.f, 0.f, 0.f);
      if (m0 + m < M)
        v = *(const float4*)(A + (size_t)(m0 + m) * F + k0 + kq * 4);
      *(float4*)&sA[m][kq * 4] = v;
    }
#pragma unroll
    for (int l = 0; l < 4; l++) {
      int idx = tid + l * 256;
      int n = idx >> 3;
      int kq = idx & 7;
      float4 v = *(const float4*)(W + (size_t)n * F + k0 + kq * 4);
      sB[kq * 4 + 0][n] = v.x;
      sB[kq * 4 + 1][n] = v.y;
      sB[kq * 4 + 2][n] = v.z;
      sB[kq * 4 + 3][n] = v.w;
    }
    __syncthreads();

#pragma unroll
    for (int kk = 0; kk < 32; kk++) {
      float b[4];
      *(float4*)b = *(const float4*)&sB[kk][tx * 4];
#pragma unroll
      for (int i = 0; i < 8; i++) {
        float a = sA[ty * 8 + i][kk];
        acc[i][0] += a * b[0];
        acc[i][1] += a * b[1];
        acc[i][2] += a * b[2];
        acc[i][3] += a * b[3];
      }
    }
    __syncthreads();
  }

  float4 bb = *(const float4*)(bias + tx * 4);
#pragma unroll
  for (int i = 0; i < 8; i++) {
    int m = m0 + ty * 8 + i;
    if (m < M) {
      float4 o;
      o.x = acc[i][0] + bb.x;
      o.y = acc[i][1] + bb.y;
      o.z = acc[i][2] + bb.z;
      o.w = acc[i][3] + bb.w;
      *(float4*)(C + (size_t)m * F + tx * 4) = o;
    }
  }
}

// ---------------- CSR gather SpMM + mean + optional ELU ----------------
// One warp per node. Lane owns features [lane*4, lane*4+4). Register
// accumulation, unroll-4 over neighbors for MLP. One coalesced 512B store.
__global__ __launch_bounds__(256) void k_gather(
    const float* __restrict__ src, float* __restrict__ dst, int apply_elu) {
  int node = blockIdx.x * 8 + (threadIdx.x >> 5);
  if (node >= NN) return;
  int lane = threadIdx.x & 31;

  int s = g_rptr[node];
  int e = g_rptr[node + 1];

  float4 acc = make_float4(0.f, 0.f, 0.f, 0.f);
  int j = s;
  for (; j + 4 <= e; j += 4) {
    int c0 = __ldg(&g_scol[j + 0]);
    int c1 = __ldg(&g_scol[j + 1]);
    int c2 = __ldg(&g_scol[j + 2]);
    int c3 = __ldg(&g_scol[j + 3]);
    float4 v0 = ((const float4*)(src + (size_t)c0 * F))[lane];
    float4 v1 = ((const float4*)(src + (size_t)c1 * F))[lane];
    float4 v2 = ((const float4*)(src + (size_t)c2 * F))[lane];
    float4 v3 = ((const float4*)(src + (size_t)c3 * F))[lane];
    acc.x += v0.x + v1.x + v2.x + v3.x;
    acc.y += v0.y + v1.y + v2.y + v3.y;
    acc.z += v0.z + v1.z + v2.z + v3.z;
    acc.w += v0.w + v1.w + v2.w + v3.w;
  }
  for (; j < e; j++) {
    int c = __ldg(&g_scol[j]);
    float4 v = ((const float4*)(src + (size_t)c * F))[lane];
    acc.x += v.x; acc.y += v.y; acc.z += v.z; acc.w += v.w;
  }

  float inv = (e > s) ? 1.0f / (float)(e - s) : 0.0f;
  acc.x *= inv; acc.y *= inv; acc.z *= inv; acc.w *= inv;
  if (apply_elu) {
    acc.x = acc.x > 0.f ? acc.x : expm1f(acc.x);
    acc.y = acc.y > 0.f ? acc.y : expm1f(acc.y);
    acc.z = acc.z > 0.f ? acc.z : expm1f(acc.z);
    acc.w = acc.w > 0.f ? acc.w : expm1f(acc.w);
  }
  ((float4*)(dst + (size_t)node * F))[lane] = acc;
}

extern "C" void kernel_launch(void* const* d_in, const int* in_sizes, int n_in,
                              void* d_out, int out_size) {
  const float* x  = (const float*)d_in[0];
  const int*   ei = (const int*)d_in[1];
  const float* W1 = (const float*)d_in[2];
  const float* b1 = (const float*)d_in[3];
  const float* W2 = (const float*)d_in[4];
  const float* b2 = (const float*)d_in[5];
  const int* row = ei;
  const int* col = ei + NE;
  float* out = (float*)d_out;

  void* p_h = nullptr;
  void* p_agg = nullptr;
  cudaGetSymbolAddress(&p_h, g_h);
  cudaGetSymbolAddress(&p_agg, g_agg);
  float* h   = (float*)p_h;
  float* agg = (float*)p_agg;

  // ---- CSR build (edge_index is shared by both SpMMs) ----
  k_zero_cnt<<<(NN + 511) / 512, 512>>>();
  k_hist<<<(NE + 511) / 512, 512>>>(row);
  k_scanA<<<NBLK, SCAN_B>>>();
  k_scanB<<<1, SCAN_B>>>();
  k_scanC<<<NBLK, SCAN_B>>>();
  k_place<<<(NE + 511) / 512, 512>>>(row, col);

  // ---- layer 1 ----
  k_gemm_bias<<<(NN + 63) / 64, 256>>>(x, W1, b1, h, NN);      // h = x W1^T + b1
  k_gather<<<(NN + 7) / 8, 256>>>(h, agg, 1);                  // agg = elu(mean-agg(h))

  // ---- layer 2 ----
  k_gemm_bias<<<(NN + 63) / 64, 256>>>(agg, W2, b2, h, NN);    // h = agg W2^T + b2
  k_gather<<<(NN + 7) / 8, 256>>>(h, out, 0);                  // out = mean-agg(h)
}

// round 4
// speedup vs baseline: 3.9598x; 1.1484x over previous
#include <cuda_runtime.h>
#include <math.h>
#include <stdint.h>

#define NN 100000
#define NE 1600000
#define F  128
#define SCAN_B 512
#define NBLK ((NN + SCAN_B - 1) / SCAN_B)   // 196

// Scratch (allocation-free rule: __device__ globals)
__device__ float g_h[(size_t)NN * F];      // 51.2 MB
__device__ float g_agg[(size_t)NN * F];    // 51.2 MB
__device__ int   g_cnt[NN];
__device__ int   g_rptr[NN + 1];
__device__ int   g_scol[NE];
__device__ int   g_part[SCAN_B];

// ================= CSR build =================
__global__ void k_zero_cnt() {
  int i = blockIdx.x * blockDim.x + threadIdx.x;
  if (i < NN) g_cnt[i] = 0;
}

__global__ void k_hist(const int* __restrict__ row) {
  int e = blockIdx.x * blockDim.x + threadIdx.x;
  if (e < NE) atomicAdd(&g_cnt[row[e]], 1);
}

__global__ __launch_bounds__(SCAN_B) void k_scanA() {
  __shared__ int sh[SCAN_B];
  int g = blockIdx.x * SCAN_B + threadIdx.x;
  int v = (g < NN) ? g_cnt[g] : 0;
  sh[threadIdx.x] = v;
  __syncthreads();
#pragma unroll
  for (int off = 1; off < SCAN_B; off <<= 1) {
    int t = (threadIdx.x >= off) ? sh[threadIdx.x - off] : 0;
    __syncthreads();
    sh[threadIdx.x] += t;
    __syncthreads();
  }
  if (g < NN) g_rptr[g] = sh[threadIdx.x] - v;
  if (threadIdx.x == SCAN_B - 1) g_part[blockIdx.x] = sh[SCAN_B - 1];
}

__global__ __launch_bounds__(SCAN_B) void k_scanB() {
  __shared__ int sh[SCAN_B];
  int v = (threadIdx.x < NBLK) ? g_part[threadIdx.x] : 0;
  sh[threadIdx.x] = v;
  __syncthreads();
#pragma unroll
  for (int off = 1; off < SCAN_B; off <<= 1) {
    int t = (threadIdx.x >= off) ? sh[threadIdx.x - off] : 0;
    __syncthreads();
    sh[threadIdx.x] += t;
    __syncthreads();
  }
  g_part[threadIdx.x] = sh[threadIdx.x] - v;
}

__global__ __launch_bounds__(SCAN_B) void k_scanC() {
  int g = blockIdx.x * SCAN_B + threadIdx.x;
  if (g < NN) {
    g_rptr[g] += g_part[blockIdx.x];
    g_cnt[g] = 0;
  }
  if (g == 0) g_rptr[NN] = NE;
}

__global__ void k_place(const int* __restrict__ row, const int* __restrict__ col) {
  int e = blockIdx.x * blockDim.x + threadIdx.x;
  if (e >= NE) return;
  int r = row[e];
  int pos = g_rptr[r] + atomicAdd(&g_cnt[r], 1);
  g_scol[pos] = col[e];
}

// ================= 3xTF32 mma.sync GEMM =================
// C[m][n] = sum_k A[m][k]*W[n][k] + bias[n]. CTA tile 128(M)x128(N), K=128 in
// two 64-halves. 8 warps: warp = 32(M)x64(N). 3xTF32 split for fp32 accuracy.

#define KT 64
#define LDS_STRIDE 68                      // 64 + 4 pad: conflict-free quads
#define TILE_FLOATS (128 * LDS_STRIDE)     // 8704
#define GEMM_SMEM (4 * TILE_FLOATS * 4)    // 139264 B

__device__ __forceinline__ uint32_t f2tf32(float x) {
  uint32_t r;
  asm("cvt.rna.tf32.f32 %0, %1;" : "=r"(r) : "f"(x));
  return r;
}

__device__ __forceinline__ void split1(float v, float& hi, float& lo) {
  hi = __uint_as_float(f2tf32(v));
  lo = __uint_as_float(f2tf32(v - hi));
}

__device__ __forceinline__ void mma_tf32(float* c, const uint32_t* a, const uint32_t* b) {
  asm volatile(
      "mma.sync.aligned.m16n8k8.row.col.f32.tf32.tf32.f32 "
      "{%0,%1,%2,%3}, {%4,%5,%6,%7}, {%8,%9}, {%0,%1,%2,%3};"
      : "+f"(c[0]), "+f"(c[1]), "+f"(c[2]), "+f"(c[3])
      : "r"(a[0]), "r"(a[1]), "r"(a[2]), "r"(a[3]), "r"(b[0]), "r"(b[1]));
}

__global__ __launch_bounds__(256, 1) void k_gemm_tc(
    const float* __restrict__ A, const float* __restrict__ W,
    const float* __restrict__ bias, float* __restrict__ C, int M) {
  extern __shared__ float sm[];
  float* sAhi = sm;
  float* sAlo = sm + TILE_FLOATS;
  float* sWhi = sm + 2 * TILE_FLOATS;
  float* sWlo = sm + 3 * TILE_FLOATS;

  const int tid = threadIdx.x;
  const int wid = tid >> 5;
  const int lane = tid & 31;
  const int wm = wid & 3;          // M group: rows [wm*32, wm*32+32)
  const int wn = wid >> 2;         // N group: cols [wn*64, wn*64+64)
  const int g = lane >> 2;         // groupID
  const int t = lane & 3;          // threadID_in_group
  const int m0 = blockIdx.x * 128;

  float acc[2][8][4];
#pragma unroll
  for (int i = 0; i < 2; i++)
#pragma unroll
    for (int j = 0; j < 8; j++)
#pragma unroll
      for (int l = 0; l < 4; l++) acc[i][j][l] = 0.0f;

  for (int half = 0; half < 2; half++) {
    const int kbase = half * KT;
    // Load + split A (128 x 64) and W (128 x 64): 2048 float4 each, 8/thread.
#pragma unroll
    for (int it = 0; it < 8; it++) {
      int idx = it * 256 + tid;
      int row = idx >> 4;
      int cq = idx & 15;
      int so = row * LDS_STRIDE + cq * 4;

      float4 va = make_float4(0.f, 0.f, 0.f, 0.f);
      if (m0 + row < M)
        va = *(const float4*)(A + (size_t)(m0 + row) * F + kbase + cq * 4);
      float4 hi, lo;
      split1(va.x, hi.x, lo.x); split1(va.y, hi.y, lo.y);
      split1(va.z, hi.z, lo.z); split1(va.w, hi.w, lo.w);
      *(float4*)&sAhi[so] = hi;
      *(float4*)&sAlo[so] = lo;

      float4 vw = *(const float4*)(W + (size_t)row * F + kbase + cq * 4);
      split1(vw.x, hi.x, lo.x); split1(vw.y, hi.y, lo.y);
      split1(vw.z, hi.z, lo.z); split1(vw.w, hi.w, lo.w);
      *(float4*)&sWhi[so] = hi;
      *(float4*)&sWlo[so] = lo;
    }
    __syncthreads();

#pragma unroll
    for (int k8 = 0; k8 < 8; k8++) {
      const int kc = k8 * 8;
      uint32_t bh[8][2], bl[8][2];
#pragma unroll
      for (int nt = 0; nt < 8; nt++) {
        int nr = (wn * 64 + nt * 8 + g) * LDS_STRIDE + kc + t;
        bh[nt][0] = __float_as_uint(sWhi[nr]);
        bh[nt][1] = __float_as_uint(sWhi[nr + 4]);
        bl[nt][0] = __float_as_uint(sWlo[nr]);
        bl[nt][1] = __float_as_uint(sWlo[nr + 4]);
      }
#pragma unroll
      for (int mt = 0; mt < 2; mt++) {
        int mr = (wm * 32 + mt * 16 + g) * LDS_STRIDE + kc + t;
        uint32_t ah[4], al[4];
        ah[0] = __float_as_uint(sAhi[mr]);
        ah[1] = __float_as_uint(sAhi[mr + 8 * LDS_STRIDE]);
        ah[2] = __float_as_uint(sAhi[mr + 4]);
        ah[3] = __float_as_uint(sAhi[mr + 8 * LDS_STRIDE + 4]);
        al[0] = __float_as_uint(sAlo[mr]);
        al[1] = __float_as_uint(sAlo[mr + 8 * LDS_STRIDE]);
        al[2] = __float_as_uint(sAlo[mr + 4]);
        al[3] = __float_as_uint(sAlo[mr + 8 * LDS_STRIDE + 4]);
#pragma unroll
        for (int nt = 0; nt < 8; nt++) {
          mma_tf32(acc[mt][nt], ah, bh[nt]);   // hi*hi
          mma_tf32(acc[mt][nt], al, bh[nt]);   // lo*hi
          mma_tf32(acc[mt][nt], ah, bl[nt]);   // hi*lo
        }
      }
    }
    __syncthreads();
  }

  // Epilogue: c0,c1 -> (row, col..col+1); c2,c3 -> (row+8, ...). 32B sectors.
#pragma unroll
  for (int mt = 0; mt < 2; mt++) {
    int row0 = m0 + wm * 32 + mt * 16 + g;
#pragma unroll
    for (int nt = 0; nt < 8; nt++) {
      int col = wn * 64 + nt * 8 + t * 2;
      float bx = __ldg(bias + col);
      float by = __ldg(bias + col + 1);
      if (row0 < M) {
        float2 o = make_float2(acc[mt][nt][0] + bx, acc[mt][nt][1] + by);
        *(float2*)(C + (size_t)row0 * F + col) = o;
      }
      if (row0 + 8 < M) {
        float2 o = make_float2(acc[mt][nt][2] + bx, acc[mt][nt][3] + by);
        *(float2*)(C + (size_t)(row0 + 8) * F + col) = o;
      }
    }
  }
}

// ================= CSR gather SpMM + mean + optional ELU =================
__global__ __launch_bounds__(256) void k_gather(
    const float* __restrict__ src, float* __restrict__ dst, int apply_elu) {
  int node = blockIdx.x * 8 + (threadIdx.x >> 5);
  if (node >= NN) return;
  int lane = threadIdx.x & 31;

  int s = g_rptr[node];
  int e = g_rptr[node + 1];

  float4 acc = make_float4(0.f, 0.f, 0.f, 0.f);
  int j = s;
  for (; j + 4 <= e; j += 4) {
    int c0 = __ldg(&g_scol[j + 0]);
    int c1 = __ldg(&g_scol[j + 1]);
    int c2 = __ldg(&g_scol[j + 2]);
    int c3 = __ldg(&g_scol[j + 3]);
    float4 v0 = ((const float4*)(src + (size_t)c0 * F))[lane];
    float4 v1 = ((const float4*)(src + (size_t)c1 * F))[lane];
    float4 v2 = ((const float4*)(src + (size_t)c2 * F))[lane];
    float4 v3 = ((const float4*)(src + (size_t)c3 * F))[lane];
    acc.x += v0.x + v1.x + v2.x + v3.x;
    acc.y += v0.y + v1.y + v2.y + v3.y;
    acc.z += v0.z + v1.z + v2.z + v3.z;
    acc.w += v0.w + v1.w + v2.w + v3.w;
  }
  for (; j < e; j++) {
    int c = __ldg(&g_scol[j]);
    float4 v = ((const float4*)(src + (size_t)c * F))[lane];
    acc.x += v.x; acc.y += v.y; acc.z += v.z; acc.w += v.w;
  }

  float inv = (e > s) ? 1.0f / (float)(e - s) : 0.0f;
  acc.x *= inv; acc.y *= inv; acc.z *= inv; acc.w *= inv;
  if (apply_elu) {
    acc.x = acc.x > 0.f ? acc.x : expm1f(acc.x);
    acc.y = acc.y > 0.f ? acc.y : expm1f(acc.y);
    acc.z = acc.z > 0.f ? acc.z : expm1f(acc.z);
    acc.w = acc.w > 0.f ? acc.w : expm1f(acc.w);
  }
  ((float4*)(dst + (size_t)node * F))[lane] = acc;
}

extern "C" void kernel_launch(void* const* d_in, const int* in_sizes, int n_in,
                              void* d_out, int out_size) {
  const float* x  = (const float*)d_in[0];
  const int*   ei = (const int*)d_in[1];
  const float* W1 = (const float*)d_in[2];
  const float* b1 = (const float*)d_in[3];
  const float* W2 = (const float*)d_in[4];
  const float* b2 = (const float*)d_in[5];
  const int* row = ei;
  const int* col = ei + NE;
  float* out = (float*)d_out;

  void* p_h = nullptr;
  void* p_agg = nullptr;
  cudaGetSymbolAddress(&p_h, g_h);
  cudaGetSymbolAddress(&p_agg, g_agg);
  float* h   = (float*)p_h;
  float* agg = (float*)p_agg;

  cudaFuncSetAttribute(k_gemm_tc, cudaFuncAttributeMaxDynamicSharedMemorySize, GEMM_SMEM);

  // ---- CSR build ----
  k_zero_cnt<<<(NN + 511) / 512, 512>>>();
  k_hist<<<(NE + 511) / 512, 512>>>(row);
  k_scanA<<<NBLK, SCAN_B>>>();
  k_scanB<<<1, SCAN_B>>>();
  k_scanC<<<NBLK, SCAN_B>>>();
  k_place<<<(NE + 511) / 512, 512>>>(row, col);

  const int gblocks = (NN + 127) / 128;   // 782
  // ---- layer 1 ----
  k_gemm_tc<<<gblocks, 256, GEMM_SMEM>>>(x, W1, b1, h, NN);
  k_gather<<<(NN + 7) / 8, 256>>>(h, agg, 1);
  // ---- layer 2 ----
  k_gemm_tc<<<gblocks, 256, GEMM_SMEM>>>(agg, W2, b2, h, NN);
  k_gather<<<(NN + 7) / 8, 256>>>(h, out, 0);
}

// round 5
// speedup vs baseline: 4.0758x; 1.0293x over previous
#include <cuda_runtime.h>
#include <math.h>
#include <stdint.h>

#define NN 100000
#define NE 1600000
#define F  128
#define SCAN_B 512
#define NBLK ((NN + SCAN_B - 1) / SCAN_B)   // 196

// Scratch (allocation-free rule: __device__ globals)
__device__ float g_h[(size_t)NN * F];      // 51.2 MB
__device__ float g_agg[(size_t)NN * F];    // 51.2 MB
__device__ int   g_cnt[NN];
__device__ int   g_rptr[NN + 1];
__device__ int   g_scol[NE];
__device__ int   g_part[SCAN_B];

// ================= CSR build =================
__global__ void k_zero_cnt() {
  int i = blockIdx.x * blockDim.x + threadIdx.x;
  if (i < NN) g_cnt[i] = 0;
}

__global__ void k_hist(const int* __restrict__ row) {
  int e = blockIdx.x * blockDim.x + threadIdx.x;
  if (e < NE) atomicAdd(&g_cnt[row[e]], 1);
}

__global__ __launch_bounds__(SCAN_B) void k_scanA() {
  __shared__ int sh[SCAN_B];
  int g = blockIdx.x * SCAN_B + threadIdx.x;
  int v = (g < NN) ? g_cnt[g] : 0;
  sh[threadIdx.x] = v;
  __syncthreads();
#pragma unroll
  for (int off = 1; off < SCAN_B; off <<= 1) {
    int t = (threadIdx.x >= off) ? sh[threadIdx.x - off] : 0;
    __syncthreads();
    sh[threadIdx.x] += t;
    __syncthreads();
  }
  if (g < NN) g_rptr[g] = sh[threadIdx.x] - v;
  if (threadIdx.x == SCAN_B - 1) g_part[blockIdx.x] = sh[SCAN_B - 1];
}

__global__ __launch_bounds__(SCAN_B) void k_scanB() {
  __shared__ int sh[SCAN_B];
  int v = (threadIdx.x < NBLK) ? g_part[threadIdx.x] : 0;
  sh[threadIdx.x] = v;
  __syncthreads();
#pragma unroll
  for (int off = 1; off < SCAN_B; off <<= 1) {
    int t = (threadIdx.x >= off) ? sh[threadIdx.x - off] : 0;
    __syncthreads();
    sh[threadIdx.x] += t;
    __syncthreads();
  }
  g_part[threadIdx.x] = sh[threadIdx.x] - v;
}

__global__ __launch_bounds__(SCAN_B) void k_scanC() {
  int g = blockIdx.x * SCAN_B + threadIdx.x;
  if (g < NN) {
    g_rptr[g] += g_part[blockIdx.x];
    g_cnt[g] = 0;
  }
  if (g == 0) g_rptr[NN] = NE;
}

__global__ void k_place(const int* __restrict__ row, const int* __restrict__ col) {
  int e = blockIdx.x * blockDim.x + threadIdx.x;
  if (e >= NE) return;
  int r = row[e];
  int pos = g_rptr[r] + atomicAdd(&g_cnt[r], 1);
  g_scol[pos] = col[e];
}

// ================= 3xTF32 mma.sync GEMM (2 CTA/SM) =================
// C[m][n] = sum_k A[m][k]*W[n][k] + bias[n]. CTA tile 128(M)x128(N), K in four
// 32-chunks (smem 73.7KB -> 2 CTAs/SM overlap load/split with MMA).
// 8 warps: warp = 32(M)x64(N). 3xTF32 split for fp32 accuracy.

#define KT 32
#define LDS_STRIDE 36                      // 32 + 4 pad
#define TILE_FLOATS (128 * LDS_STRIDE)     // 4608
#define GEMM_SMEM (4 * TILE_FLOATS * 4)    // 73728 B

__device__ __forceinline__ uint32_t f2tf32(float x) {
  uint32_t r;
  asm("cvt.rna.tf32.f32 %0, %1;" : "=r"(r) : "f"(x));
  return r;
}

__device__ __forceinline__ void split1(float v, float& hi, float& lo) {
  hi = __uint_as_float(f2tf32(v));
  lo = __uint_as_float(f2tf32(v - hi));
}

__device__ __forceinline__ void mma_tf32(float* c, const uint32_t* a, const uint32_t* b) {
  asm volatile(
      "mma.sync.aligned.m16n8k8.row.col.f32.tf32.tf32.f32 "
      "{%0,%1,%2,%3}, {%4,%5,%6,%7}, {%8,%9}, {%0,%1,%2,%3};"
      : "+f"(c[0]), "+f"(c[1]), "+f"(c[2]), "+f"(c[3])
      : "r"(a[0]), "r"(a[1]), "r"(a[2]), "r"(a[3]), "r"(b[0]), "r"(b[1]));
}

__global__ __launch_bounds__(256, 2) void k_gemm_tc(
    const float* __restrict__ A, const float* __restrict__ W,
    const float* __restrict__ bias, float* __restrict__ C, int M) {
  extern __shared__ float sm[];
  float* sAhi = sm;
  float* sAlo = sm + TILE_FLOATS;
  float* sWhi = sm + 2 * TILE_FLOATS;
  float* sWlo = sm + 3 * TILE_FLOATS;

  const int tid = threadIdx.x;
  const int wid = tid >> 5;
  const int lane = tid & 31;
  const int wm = wid & 3;          // M group: rows [wm*32, wm*32+32)
  const int wn = wid >> 2;         // N group: cols [wn*64, wn*64+64)
  const int g = lane >> 2;         // groupID
  const int t = lane & 3;          // threadID_in_group
  const int m0 = blockIdx.x * 128;

  float acc[2][8][4];
#pragma unroll
  for (int i = 0; i < 2; i++)
#pragma unroll
    for (int j = 0; j < 8; j++)
#pragma unroll
      for (int l = 0; l < 4; l++) acc[i][j][l] = 0.0f;

#pragma unroll 1
  for (int chunk = 0; chunk < 4; chunk++) {
    const int kbase = chunk * KT;
    // Load + split A (128x32) and W (128x32): 1024 float4 each, 4/thread.
#pragma unroll
    for (int it = 0; it < 4; it++) {
      int idx = it * 256 + tid;
      int row = idx >> 3;
      int cq = idx & 7;
      int so = row * LDS_STRIDE + cq * 4;

      float4 va = make_float4(0.f, 0.f, 0.f, 0.f);
      if (m0 + row < M)
        va = *(const float4*)(A + (size_t)(m0 + row) * F + kbase + cq * 4);
      float4 hi, lo;
      split1(va.x, hi.x, lo.x); split1(va.y, hi.y, lo.y);
      split1(va.z, hi.z, lo.z); split1(va.w, hi.w, lo.w);
      *(float4*)&sAhi[so] = hi;
      *(float4*)&sAlo[so] = lo;

      float4 vw = *(const float4*)(W + (size_t)row * F + kbase + cq * 4);
      split1(vw.x, hi.x, lo.x); split1(vw.y, hi.y, lo.y);
      split1(vw.z, hi.z, lo.z); split1(vw.w, hi.w, lo.w);
      *(float4*)&sWhi[so] = hi;
      *(float4*)&sWlo[so] = lo;
    }
    __syncthreads();

#pragma unroll
    for (int k8 = 0; k8 < 4; k8++) {
      const int kc = k8 * 8;
      // A fragments for both 16-row subtiles (held across nt loop)
      uint32_t ah[2][4], al[2][4];
#pragma unroll
      for (int mt = 0; mt < 2; mt++) {
        int mr = (wm * 32 + mt * 16 + g) * LDS_STRIDE + kc + t;
        ah[mt][0] = __float_as_uint(sAhi[mr]);
        ah[mt][1] = __float_as_uint(sAhi[mr + 8 * LDS_STRIDE]);
        ah[mt][2] = __float_as_uint(sAhi[mr + 4]);
        ah[mt][3] = __float_as_uint(sAhi[mr + 8 * LDS_STRIDE + 4]);
        al[mt][0] = __float_as_uint(sAlo[mr]);
        al[mt][1] = __float_as_uint(sAlo[mr + 8 * LDS_STRIDE]);
        al[mt][2] = __float_as_uint(sAlo[mr + 4]);
        al[mt][3] = __float_as_uint(sAlo[mr + 8 * LDS_STRIDE + 4]);
      }
#pragma unroll
      for (int nt = 0; nt < 8; nt++) {
        int nr = (wn * 64 + nt * 8 + g) * LDS_STRIDE + kc + t;
        uint32_t bh[2], bl[2];
        bh[0] = __float_as_uint(sWhi[nr]);
        bh[1] = __float_as_uint(sWhi[nr + 4]);
        bl[0] = __float_as_uint(sWlo[nr]);
        bl[1] = __float_as_uint(sWlo[nr + 4]);
#pragma unroll
        for (int mt = 0; mt < 2; mt++) {
          mma_tf32(acc[mt][nt], ah[mt], bh);   // hi*hi
          mma_tf32(acc[mt][nt], al[mt], bh);   // lo*hi
          mma_tf32(acc[mt][nt], ah[mt], bl);   // hi*lo
        }
      }
    }
    __syncthreads();
  }

  // Epilogue: c0,c1 -> (row, col..col+1); c2,c3 -> (row+8, ...).
#pragma unroll
  for (int mt = 0; mt < 2; mt++) {
    int row0 = m0 + wm * 32 + mt * 16 + g;
#pragma unroll
    for (int nt = 0; nt < 8; nt++) {
      int col = wn * 64 + nt * 8 + t * 2;
      float bx = __ldg(bias + col);
      float by = __ldg(bias + col + 1);
      if (row0 < M) {
        float2 o = make_float2(acc[mt][nt][0] + bx, acc[mt][nt][1] + by);
        *(float2*)(C + (size_t)row0 * F + col) = o;
      }
      if (row0 + 8 < M) {
        float2 o = make_float2(acc[mt][nt][2] + bx, acc[mt][nt][3] + by);
        *(float2*)(C + (size_t)(row0 + 8) * F + col) = o;
      }
    }
  }
}

// ================= CSR gather SpMM + mean + optional ELU =================
__global__ __launch_bounds__(256) void k_gather(
    const float* __restrict__ src, float* __restrict__ dst, int apply_elu) {
  int node = blockIdx.x * 8 + (threadIdx.x >> 5);
  if (node >= NN) return;
  int lane = threadIdx.x & 31;

  int s = g_rptr[node];
  int e = g_rptr[node + 1];

  float4 acc = make_float4(0.f, 0.f, 0.f, 0.f);
  int j = s;
  for (; j + 4 <= e; j += 4) {
    int c0 = __ldg(&g_scol[j + 0]);
    int c1 = __ldg(&g_scol[j + 1]);
    int c2 = __ldg(&g_scol[j + 2]);
    int c3 = __ldg(&g_scol[j + 3]);
    float4 v0 = ((const float4*)(src + (size_t)c0 * F))[lane];
    float4 v1 = ((const float4*)(src + (size_t)c1 * F))[lane];
    float4 v2 = ((const float4*)(src + (size_t)c2 * F))[lane];
    float4 v3 = ((const float4*)(src + (size_t)c3 * F))[lane];
    acc.x += v0.x + v1.x + v2.x + v3.x;
    acc.y += v0.y + v1.y + v2.y + v3.y;
    acc.z += v0.z + v1.z + v2.z + v3.z;
    acc.w += v0.w + v1.w + v2.w + v3.w;
  }
  for (; j < e; j++) {
    int c = __ldg(&g_scol[j]);
    float4 v = ((const float4*)(src + (size_t)c * F))[lane];
    acc.x += v.x; acc.y += v.y; acc.z += v.z; acc.w += v.w;
  }

  float inv = (e > s) ? 1.0f / (float)(e - s) : 0.0f;
  acc.x *= inv; acc.y *= inv; acc.z *= inv; acc.w *= inv;
  if (apply_elu) {
    acc.x = acc.x > 0.f ? acc.x : expm1f(acc.x);
    acc.y = acc.y > 0.f ? acc.y : expm1f(acc.y);
    acc.z = acc.z > 0.f ? acc.z : expm1f(acc.z);
    acc.w = acc.w > 0.f ? acc.w : expm1f(acc.w);
  }
  ((float4*)(dst + (size_t)node * F))[lane] = acc;
}

extern "C" void kernel_launch(void* const* d_in, const int* in_sizes, int n_in,
                              void* d_out, int out_size) {
  const float* x  = (const float*)d_in[0];
  const int*   ei = (const int*)d_in[1];
  const float* W1 = (const float*)d_in[2];
  const float* b1 = (const float*)d_in[3];
  const float* W2 = (const float*)d_in[4];
  const float* b2 = (const float*)d_in[5];
  const int* row = ei;
  const int* col = ei + NE;
  float* out = (float*)d_out;

  void* p_h = nullptr;
  void* p_agg = nullptr;
  cudaGetSymbolAddress(&p_h, g_h);
  cudaGetSymbolAddress(&p_agg, g_agg);
  float* h   = (float*)p_h;
  float* agg = (float*)p_agg;

  cudaFuncSetAttribute(k_gemm_tc, cudaFuncAttributeMaxDynamicSharedMemorySize, GEMM_SMEM);

  // ---- CSR build ----
  k_zero_cnt<<<(NN + 511) / 512, 512>>>();
  k_hist<<<(NE + 511) / 512, 512>>>(row);
  k_scanA<<<NBLK, SCAN_B>>>();
  k_scanB<<<1, SCAN_B>>>();
  k_scanC<<<NBLK, SCAN_B>>>();
  k_place<<<(NE + 511) / 512, 512>>>(row, col);

  const int gblocks = (NN + 127) / 128;   // 782
  // ---- layer 1 ----
  k_gemm_tc<<<gblocks, 256, GEMM_SMEM>>>(x, W1, b1, h, NN);
  k_gather<<<(NN + 7) / 8, 256>>>(h, agg, 1);
  // ---- layer 2 ----
  k_gemm_tc<<<gblocks, 256, GEMM_SMEM>>>(agg, W2, b2, h, NN);
  k_gather<<<(NN + 7) / 8, 256>>>(h, out, 0);
}

// round 6
// speedup vs baseline: 4.5673x; 1.1206x over previous
#include <cuda_runtime.h>
#include <cuda_fp16.h>
#include <math.h>
#include <stdint.h>

#define NN 100000
#define NE 1600000
#define F  128
#define SCAN_B 512
#define NBLK ((NN + SCAN_B - 1) / SCAN_B)   // 196

// Scratch (allocation-free rule: __device__ globals)
__device__ __half g_h[(size_t)NN * F];     // 25.6 MB (fp16 intermediate)
__device__ float  g_agg[(size_t)NN * F];   // 51.2 MB
__device__ int    g_cnt[NN];
__device__ int    g_rptr[NN + 1];
__device__ int    g_scol[NE];
__device__ int    g_part[SCAN_B];

// ================= CSR build =================
__global__ void k_zero_cnt() {
  int i = blockIdx.x * blockDim.x + threadIdx.x;
  if (i < NN) g_cnt[i] = 0;
}

__global__ void k_hist(const int* __restrict__ row) {
  int e = blockIdx.x * blockDim.x + threadIdx.x;
  if (e < NE) atomicAdd(&g_cnt[row[e]], 1);
}

__global__ __launch_bounds__(SCAN_B) void k_scanA() {
  __shared__ int sh[SCAN_B];
  int g = blockIdx.x * SCAN_B + threadIdx.x;
  int v = (g < NN) ? g_cnt[g] : 0;
  sh[threadIdx.x] = v;
  __syncthreads();
#pragma unroll
  for (int off = 1; off < SCAN_B; off <<= 1) {
    int t = (threadIdx.x >= off) ? sh[threadIdx.x - off] : 0;
    __syncthreads();
    sh[threadIdx.x] += t;
    __syncthreads();
  }
  if (g < NN) g_rptr[g] = sh[threadIdx.x] - v;
  if (threadIdx.x == SCAN_B - 1) g_part[blockIdx.x] = sh[SCAN_B - 1];
}

__global__ __launch_bounds__(SCAN_B) void k_scanB() {
  __shared__ int sh[SCAN_B];
  int v = (threadIdx.x < NBLK) ? g_part[threadIdx.x] : 0;
  sh[threadIdx.x] = v;
  __syncthreads();
#pragma unroll
  for (int off = 1; off < SCAN_B; off <<= 1) {
    int t = (threadIdx.x >= off) ? sh[threadIdx.x - off] : 0;
    __syncthreads();
    sh[threadIdx.x] += t;
    __syncthreads();
  }
  g_part[threadIdx.x] = sh[threadIdx.x] - v;
}

__global__ __launch_bounds__(SCAN_B) void k_scanC() {
  int g = blockIdx.x * SCAN_B + threadIdx.x;
  if (g < NN) {
    g_rptr[g] += g_part[blockIdx.x];
    g_cnt[g] = 0;
  }
  if (g == 0) g_rptr[NN] = NE;
}

__global__ void k_place(const int* __restrict__ row, const int* __restrict__ col) {
  int e = blockIdx.x * blockDim.x + threadIdx.x;
  if (e >= NE) return;
  int r = row[e];
  int pos = g_rptr[r] + atomicAdd(&g_cnt[r], 1);
  g_scol[pos] = col[e];
}

// ================= 3xTF32 mma.sync GEMM (2 CTA/SM), fp16 output =================
#define KT 32
#define LDS_STRIDE 36
#define TILE_FLOATS (128 * LDS_STRIDE)     // 4608
#define GEMM_SMEM (4 * TILE_FLOATS * 4)    // 73728 B

__device__ __forceinline__ uint32_t f2tf32(float x) {
  uint32_t r;
  asm("cvt.rna.tf32.f32 %0, %1;" : "=r"(r) : "f"(x));
  return r;
}

__device__ __forceinline__ void split1(float v, float& hi, float& lo) {
  hi = __uint_as_float(f2tf32(v));
  lo = __uint_as_float(f2tf32(v - hi));
}

__device__ __forceinline__ void mma_tf32(float* c, const uint32_t* a, const uint32_t* b) {
  asm volatile(
      "mma.sync.aligned.m16n8k8.row.col.f32.tf32.tf32.f32 "
      "{%0,%1,%2,%3}, {%4,%5,%6,%7}, {%8,%9}, {%0,%1,%2,%3};"
      : "+f"(c[0]), "+f"(c[1]), "+f"(c[2]), "+f"(c[3])
      : "r"(a[0]), "r"(a[1]), "r"(a[2]), "r"(a[3]), "r"(b[0]), "r"(b[1]));
}

__global__ __launch_bounds__(256, 2) void k_gemm_tc(
    const float* __restrict__ A, const float* __restrict__ W,
    const float* __restrict__ bias, __half* __restrict__ C, int M) {
  extern __shared__ float sm[];
  float* sAhi = sm;
  float* sAlo = sm + TILE_FLOATS;
  float* sWhi = sm + 2 * TILE_FLOATS;
  float* sWlo = sm + 3 * TILE_FLOATS;

  const int tid = threadIdx.x;
  const int wid = tid >> 5;
  const int lane = tid & 31;
  const int wm = wid & 3;
  const int wn = wid >> 2;
  const int g = lane >> 2;
  const int t = lane & 3;
  const int m0 = blockIdx.x * 128;

  float acc[2][8][4];
#pragma unroll
  for (int i = 0; i < 2; i++)
#pragma unroll
    for (int j = 0; j < 8; j++)
#pragma unroll
      for (int l = 0; l < 4; l++) acc[i][j][l] = 0.0f;

#pragma unroll 1
  for (int chunk = 0; chunk < 4; chunk++) {
    const int kbase = chunk * KT;
#pragma unroll
    for (int it = 0; it < 4; it++) {
      int idx = it * 256 + tid;
      int row = idx >> 3;
      int cq = idx & 7;
      int so = row * LDS_STRIDE + cq * 4;

      float4 va = make_float4(0.f, 0.f, 0.f, 0.f);
      if (m0 + row < M)
        va = *(const float4*)(A + (size_t)(m0 + row) * F + kbase + cq * 4);
      float4 hi, lo;
      split1(va.x, hi.x, lo.x); split1(va.y, hi.y, lo.y);
      split1(va.z, hi.z, lo.z); split1(va.w, hi.w, lo.w);
      *(float4*)&sAhi[so] = hi;
      *(float4*)&sAlo[so] = lo;

      float4 vw = *(const float4*)(W + (size_t)row * F + kbase + cq * 4);
      split1(vw.x, hi.x, lo.x); split1(vw.y, hi.y, lo.y);
      split1(vw.z, hi.z, lo.z); split1(vw.w, hi.w, lo.w);
      *(float4*)&sWhi[so] = hi;
      *(float4*)&sWlo[so] = lo;
    }
    __syncthreads();

#pragma unroll
    for (int k8 = 0; k8 < 4; k8++) {
      const int kc = k8 * 8;
      uint32_t ah[2][4], al[2][4];
#pragma unroll
      for (int mt = 0; mt < 2; mt++) {
        int mr = (wm * 32 + mt * 16 + g) * LDS_STRIDE + kc + t;
        ah[mt][0] = __float_as_uint(sAhi[mr]);
        ah[mt][1] = __float_as_uint(sAhi[mr + 8 * LDS_STRIDE]);
        ah[mt][2] = __float_as_uint(sAhi[mr + 4]);
        ah[mt][3] = __float_as_uint(sAhi[mr + 8 * LDS_STRIDE + 4]);
        al[mt][0] = __float_as_uint(sAlo[mr]);
        al[mt][1] = __float_as_uint(sAlo[mr + 8 * LDS_STRIDE]);
        al[mt][2] = __float_as_uint(sAlo[mr + 4]);
        al[mt][3] = __float_as_uint(sAlo[mr + 8 * LDS_STRIDE + 4]);
      }
#pragma unroll
      for (int nt = 0; nt < 8; nt++) {
        int nr = (wn * 64 + nt * 8 + g) * LDS_STRIDE + kc + t;
        uint32_t bh[2], bl[2];
        bh[0] = __float_as_uint(sWhi[nr]);
        bh[1] = __float_as_uint(sWhi[nr + 4]);
        bl[0] = __float_as_uint(sWlo[nr]);
        bl[1] = __float_as_uint(sWlo[nr + 4]);
#pragma unroll
        for (int mt = 0; mt < 2; mt++) {
          mma_tf32(acc[mt][nt], ah[mt], bh);
          mma_tf32(acc[mt][nt], al[mt], bh);
          mma_tf32(acc[mt][nt], ah[mt], bl);
        }
      }
    }
    __syncthreads();
  }

  // Epilogue: fp16 store (half2 per fragment pair)
#pragma unroll
  for (int mt = 0; mt < 2; mt++) {
    int row0 = m0 + wm * 32 + mt * 16 + g;
#pragma unroll
    for (int nt = 0; nt < 8; nt++) {
      int col = wn * 64 + nt * 8 + t * 2;
      float bx = __ldg(bias + col);
      float by = __ldg(bias + col + 1);
      if (row0 < M) {
        __half2 o = __floats2half2_rn(acc[mt][nt][0] + bx, acc[mt][nt][1] + by);
        *(__half2*)(C + (size_t)row0 * F + col) = o;
      }
      if (row0 + 8 < M) {
        __half2 o = __floats2half2_rn(acc[mt][nt][2] + bx, acc[mt][nt][3] + by);
        *(__half2*)(C + (size_t)(row0 + 8) * F + col) = o;
      }
    }
  }
}

// ================= CSR gather SpMM (fp16 src) + mean + optional ELU =================
// One warp per node; lane owns features [lane*4, lane*4+4) as 4 halves (uint2).
__device__ __forceinline__ void acc_edge(float4& acc, const __half* src, int c, int lane) {
  uint2 v = ((const uint2*)(src + (size_t)c * F))[lane];
  float2 f0 = __half22float2(*(__half2*)&v.x);
  float2 f1 = __half22float2(*(__half2*)&v.y);
  acc.x += f0.x; acc.y += f0.y; acc.z += f1.x; acc.w += f1.y;
}

__global__ __launch_bounds__(256) void k_gather(
    const __half* __restrict__ src, float* __restrict__ dst, int apply_elu) {
  int node = blockIdx.x * 8 + (threadIdx.x >> 5);
  if (node >= NN) return;
  int lane = threadIdx.x & 31;

  int s = g_rptr[node];
  int e = g_rptr[node + 1];

  float4 acc = make_float4(0.f, 0.f, 0.f, 0.f);
  int j = s;
  for (; j + 4 <= e; j += 4) {
    int c0 = __ldg(&g_scol[j + 0]);
    int c1 = __ldg(&g_scol[j + 1]);
    int c2 = __ldg(&g_scol[j + 2]);
    int c3 = __ldg(&g_scol[j + 3]);
    acc_edge(acc, src, c0, lane);
    acc_edge(acc, src, c1, lane);
    acc_edge(acc, src, c2, lane);
    acc_edge(acc, src, c3, lane);
  }
  for (; j < e; j++) {
    int c = __ldg(&g_scol[j]);
    acc_edge(acc, src, c, lane);
  }

  float inv = (e > s) ? 1.0f / (float)(e - s) : 0.0f;
  acc.x *= inv; acc.y *= inv; acc.z *= inv; acc.w *= inv;
  if (apply_elu) {
    acc.x = acc.x > 0.f ? acc.x : expm1f(acc.x);
    acc.y = acc.y > 0.f ? acc.y : expm1f(acc.y);
    acc.z = acc.z > 0.f ? acc.z : expm1f(acc.z);
    acc.w = acc.w > 0.f ? acc.w : expm1f(acc.w);
  }
  ((float4*)(dst + (size_t)node * F))[lane] = acc;
}

extern "C" void kernel_launch(void* const* d_in, const int* in_sizes, int n_in,
                              void* d_out, int out_size) {
  const float* x  = (const float*)d_in[0];
  const int*   ei = (const int*)d_in[1];
  const float* W1 = (const float*)d_in[2];
  const float* b1 = (const float*)d_in[3];
  const float* W2 = (const float*)d_in[4];
  const float* b2 = (const float*)d_in[5];
  const int* row = ei;
  const int* col = ei + NE;
  float* out = (float*)d_out;

  void* p_h = nullptr;
  void* p_agg = nullptr;
  cudaGetSymbolAddress(&p_h, g_h);
  cudaGetSymbolAddress(&p_agg, g_agg);
  __half* h  = (__half*)p_h;
  float* agg = (float*)p_agg;

  cudaFuncSetAttribute(k_gemm_tc, cudaFuncAttributeMaxDynamicSharedMemorySize, GEMM_SMEM);

  // ---- CSR build ----
  k_zero_cnt<<<(NN + 511) / 512, 512>>>();
  k_hist<<<(NE + 511) / 512, 512>>>(row);
  k_scanA<<<NBLK, SCAN_B>>>();
  k_scanB<<<1, SCAN_B>>>();
  k_scanC<<<NBLK, SCAN_B>>>();
  k_place<<<(NE + 511) / 512, 512>>>(row, col);

  const int gblocks = (NN + 127) / 128;   // 782
  // ---- layer 1 ----
  k_gemm_tc<<<gblocks, 256, GEMM_SMEM>>>(x, W1, b1, h, NN);
  k_gather<<<(NN + 7) / 8, 256>>>(h, agg, 1);
  // ---- layer 2 ----
  k_gemm_tc<<<gblocks, 256, GEMM_SMEM>>>(agg, W2, b2, h, NN);
  k_gather<<<(NN + 7) / 8, 256>>>(h, out, 0);
}

// round 7
// speedup vs baseline: 6.8410x; 1.4978x over previous
#include <cuda_runtime.h>
#include <cuda_fp16.h>
#include <math.h>
#include <stdint.h>

#define NN 100000
#define NE 1600000
#define F  128
#define SCAN_B 512
#define NBLK ((NN + SCAN_B - 1) / SCAN_B)   // 196

// Scratch (allocation-free rule: __device__ globals)
__device__ __half g_h[(size_t)NN * F];     // 25.6 MB (fp16 intermediate)
__device__ float  g_agg[(size_t)NN * F];   // 51.2 MB
__device__ int    g_cnt[NN];
__device__ int    g_rptr[NN + 1];
__device__ int    g_scol[NE];
__device__ int    g_part[SCAN_B];

// ================= CSR build =================
__global__ void k_zero_cnt() {
  int i = blockIdx.x * blockDim.x + threadIdx.x;
  if (i < NN) g_cnt[i] = 0;
}

__global__ void k_hist(const int* __restrict__ row) {
  int e = blockIdx.x * blockDim.x + threadIdx.x;
  if (e < NE) atomicAdd(&g_cnt[row[e]], 1);
}

__global__ __launch_bounds__(SCAN_B) void k_scanA() {
  __shared__ int sh[SCAN_B];
  int g = blockIdx.x * SCAN_B + threadIdx.x;
  int v = (g < NN) ? g_cnt[g] : 0;
  sh[threadIdx.x] = v;
  __syncthreads();
#pragma unroll
  for (int off = 1; off < SCAN_B; off <<= 1) {
    int t = (threadIdx.x >= off) ? sh[threadIdx.x - off] : 0;
    __syncthreads();
    sh[threadIdx.x] += t;
    __syncthreads();
  }
  if (g < NN) g_rptr[g] = sh[threadIdx.x] - v;
  if (threadIdx.x == SCAN_B - 1) g_part[blockIdx.x] = sh[SCAN_B - 1];
}

__global__ __launch_bounds__(SCAN_B) void k_scanB() {
  __shared__ int sh[SCAN_B];
  int v = (threadIdx.x < NBLK) ? g_part[threadIdx.x] : 0;
  sh[threadIdx.x] = v;
  __syncthreads();
#pragma unroll
  for (int off = 1; off < SCAN_B; off <<= 1) {
    int t = (threadIdx.x >= off) ? sh[threadIdx.x - off] : 0;
    __syncthreads();
    sh[threadIdx.x] += t;
    __syncthreads();
  }
  g_part[threadIdx.x] = sh[threadIdx.x] - v;
}

__global__ __launch_bounds__(SCAN_B) void k_scanC() {
  int g = blockIdx.x * SCAN_B + threadIdx.x;
  if (g < NN) {
    g_rptr[g] += g_part[blockIdx.x];
    g_cnt[g] = 0;
  }
  if (g == 0) g_rptr[NN] = NE;
}

__global__ void k_place(const int* __restrict__ row, const int* __restrict__ col) {
  int e = blockIdx.x * blockDim.x + threadIdx.x;
  if (e >= NE) return;
  int r = row[e];
  int pos = g_rptr[r] + atomicAdd(&g_cnt[r], 1);
  g_scol[pos] = col[e];
}

// ================= fp16 mma.sync GEMM (single pass, 2 CTA/SM) =================
// C[m][n] = sum_k A[m][k]*W[n][k] + bias[n]. CTA tile 128x128, full K=128 in
// SMEM as fp16 (A and W converted on load). 8 warps: warp = 32(M)x64(N).
// mma.sync.m16n8k16.f32.f16.f16.f32, fp32 accumulate, fp16 output.

#define H_STRIDE 136                        // halves per row (128 + 8 pad)
#define TILE_HALVES (128 * H_STRIDE)        // 17408
#define GEMM_SMEM (2 * TILE_HALVES * 2)     // 69632 B

__device__ __forceinline__ void mma_f16(float* c, const uint32_t* a, const uint32_t* b) {
  asm volatile(
      "mma.sync.aligned.m16n8k16.row.col.f32.f16.f16.f32 "
      "{%0,%1,%2,%3}, {%4,%5,%6,%7}, {%8,%9}, {%0,%1,%2,%3};"
      : "+f"(c[0]), "+f"(c[1]), "+f"(c[2]), "+f"(c[3])
      : "r"(a[0]), "r"(a[1]), "r"(a[2]), "r"(a[3]), "r"(b[0]), "r"(b[1]));
}

__global__ __launch_bounds__(256, 2) void k_gemm_tc(
    const float* __restrict__ A, const float* __restrict__ W,
    const float* __restrict__ bias, __half* __restrict__ C, int M) {
  extern __shared__ __half sh[];
  __half* sA = sh;                 // [128][H_STRIDE]
  __half* sW = sh + TILE_HALVES;   // [128][H_STRIDE]

  const int tid = threadIdx.x;
  const int wid = tid >> 5;
  const int lane = tid & 31;
  const int wm = wid & 3;          // M group: rows [wm*32, wm*32+32)
  const int wn = wid >> 2;         // N group: cols [wn*64, wn*64+64)
  const int g = lane >> 2;
  const int t = lane & 3;
  const int m0 = blockIdx.x * 128;

  // Load + convert A (128x128 f32 -> f16) and W. 4096 float4 each, 16/thread.
#pragma unroll
  for (int it = 0; it < 16; it++) {
    int idx = it * 256 + tid;
    int row = idx >> 5;
    int cq = idx & 31;               // float4 index within row

    float4 va = make_float4(0.f, 0.f, 0.f, 0.f);
    if (m0 + row < M)
      va = *(const float4*)(A + (size_t)(m0 + row) * F + cq * 4);
    __half2 h0 = __floats2half2_rn(va.x, va.y);
    __half2 h1 = __floats2half2_rn(va.z, va.w);
    *(__half2*)&sA[row * H_STRIDE + cq * 4]     = h0;
    *(__half2*)&sA[row * H_STRIDE + cq * 4 + 2] = h1;

    float4 vw = *(const float4*)(W + (size_t)row * F + cq * 4);
    h0 = __floats2half2_rn(vw.x, vw.y);
    h1 = __floats2half2_rn(vw.z, vw.w);
    *(__half2*)&sW[row * H_STRIDE + cq * 4]     = h0;
    *(__half2*)&sW[row * H_STRIDE + cq * 4 + 2] = h1;
  }
  __syncthreads();

  float acc[2][8][4];
#pragma unroll
  for (int i = 0; i < 2; i++)
#pragma unroll
    for (int j = 0; j < 8; j++)
#pragma unroll
      for (int l = 0; l < 4; l++) acc[i][j][l] = 0.0f;

#pragma unroll
  for (int k16 = 0; k16 < 8; k16++) {
    const int kc = k16 * 16;
    // A fragments for both 16-row subtiles
    uint32_t af[2][4];
#pragma unroll
    for (int mt = 0; mt < 2; mt++) {
      const __half* base = sA + (size_t)(wm * 32 + mt * 16 + g) * H_STRIDE + kc;
      af[mt][0] = *(const uint32_t*)(base + 2 * t);
      af[mt][1] = *(const uint32_t*)(base + 8 * H_STRIDE + 2 * t);
      af[mt][2] = *(const uint32_t*)(base + 2 * t + 8);
      af[mt][3] = *(const uint32_t*)(base + 8 * H_STRIDE + 2 * t + 8);
    }
#pragma unroll
    for (int nt = 0; nt < 8; nt++) {
      const __half* wbase = sW + (size_t)(wn * 64 + nt * 8 + g) * H_STRIDE + kc;
      uint32_t bf[2];
      bf[0] = *(const uint32_t*)(wbase + 2 * t);
      bf[1] = *(const uint32_t*)(wbase + 2 * t + 8);
#pragma unroll
      for (int mt = 0; mt < 2; mt++) mma_f16(acc[mt][nt], af[mt], bf);
    }
  }

  // Epilogue: fp16 store (half2 per fragment pair)
#pragma unroll
  for (int mt = 0; mt < 2; mt++) {
    int row0 = m0 + wm * 32 + mt * 16 + g;
#pragma unroll
    for (int nt = 0; nt < 8; nt++) {
      int col = wn * 64 + nt * 8 + t * 2;
      float bx = __ldg(bias + col);
      float by = __ldg(bias + col + 1);
      if (row0 < M) {
        __half2 o = __floats2half2_rn(acc[mt][nt][0] + bx, acc[mt][nt][1] + by);
        *(__half2*)(C + (size_t)row0 * F + col) = o;
      }
      if (row0 + 8 < M) {
        __half2 o = __floats2half2_rn(acc[mt][nt][2] + bx, acc[mt][nt][3] + by);
        *(__half2*)(C + (size_t)(row0 + 8) * F + col) = o;
      }
    }
  }
}

// ================= CSR gather SpMM (fp16 src) + mean + optional ELU =================
__device__ __forceinline__ void acc_edge(float4& acc, const __half* src, int c, int lane) {
  uint2 v = ((const uint2*)(src + (size_t)c * F))[lane];
  float2 f0 = __half22float2(*(__half2*)&v.x);
  float2 f1 = __half22float2(*(__half2*)&v.y);
  acc.x += f0.x; acc.y += f0.y; acc.z += f1.x; acc.w += f1.y;
}

__global__ __launch_bounds__(256) void k_gather(
    const __half* __restrict__ src, float* __restrict__ dst, int apply_elu) {
  int node = blockIdx.x * 8 + (threadIdx.x >> 5);
  if (node >= NN) return;
  int lane = threadIdx.x & 31;

  int s = g_rptr[node];
  int e = g_rptr[node + 1];

  float4 acc = make_float4(0.f, 0.f, 0.f, 0.f);
  int j = s;
  for (; j + 4 <= e; j += 4) {
    int c0 = __ldg(&g_scol[j + 0]);
    int c1 = __ldg(&g_scol[j + 1]);
    int c2 = __ldg(&g_scol[j + 2]);
    int c3 = __ldg(&g_scol[j + 3]);
    acc_edge(acc, src, c0, lane);
    acc_edge(acc, src, c1, lane);
    acc_edge(acc, src, c2, lane);
    acc_edge(acc, src, c3, lane);
  }
  for (; j < e; j++) {
    int c = __ldg(&g_scol[j]);
    acc_edge(acc, src, c, lane);
  }

  float inv = (e > s) ? 1.0f / (float)(e - s) : 0.0f;
  acc.x *= inv; acc.y *= inv; acc.z *= inv; acc.w *= inv;
  if (apply_elu) {
    acc.x = acc.x > 0.f ? acc.x : expm1f(acc.x);
    acc.y = acc.y > 0.f ? acc.y : expm1f(acc.y);
    acc.z = acc.z > 0.f ? acc.z : expm1f(acc.z);
    acc.w = acc.w > 0.f ? acc.w : expm1f(acc.w);
  }
  ((float4*)(dst + (size_t)node * F))[lane] = acc;
}

extern "C" void kernel_launch(void* const* d_in, const int* in_sizes, int n_in,
                              void* d_out, int out_size) {
  const float* x  = (const float*)d_in[0];
  const int*   ei = (const int*)d_in[1];
  const float* W1 = (const float*)d_in[2];
  const float* b1 = (const float*)d_in[3];
  const float* W2 = (const float*)d_in[4];
  const float* b2 = (const float*)d_in[5];
  const int* row = ei;
  const int* col = ei + NE;
  float* out = (float*)d_out;

  void* p_h = nullptr;
  void* p_agg = nullptr;
  cudaGetSymbolAddress(&p_h, g_h);
  cudaGetSymbolAddress(&p_agg, g_agg);
  __half* h  = (__half*)p_h;
  float* agg = (float*)p_agg;

  cudaFuncSetAttribute(k_gemm_tc, cudaFuncAttributeMaxDynamicSharedMemorySize, GEMM_SMEM);

  // ---- CSR build ----
  k_zero_cnt<<<(NN + 511) / 512, 512>>>();
  k_hist<<<(NE + 511) / 512, 512>>>(row);
  k_scanA<<<NBLK, SCAN_B>>>();
  k_scanB<<<1, SCAN_B>>>();
  k_scanC<<<NBLK, SCAN_B>>>();
  k_place<<<(NE + 511) / 512, 512>>>(row, col);

  const int gblocks = (NN + 127) / 128;   // 782
  // ---- layer 1 ----
  k_gemm_tc<<<gblocks, 256, GEMM_SMEM>>>(x, W1, b1, h, NN);
  k_gather<<<(NN + 7) / 8, 256>>>(h, agg, 1);
  // ---- layer 2 ----
  k_gemm_tc<<<gblocks, 256, GEMM_SMEM>>>(agg, W2, b2, h, NN);
  k_gather<<<(NN + 7) / 8, 256>>>(h, out, 0);
}

// round 8
// speedup vs baseline: 7.1360x; 1.0431x over previous
#include <cuda_runtime.h>
#include <cuda_fp16.h>
#include <math.h>
#include <stdint.h>

#define NN 100000
#define NE 1600000
#define F  128
#define SCAN_B 512
#define NBLK ((NN + SCAN_B - 1) / SCAN_B)   // 196

// Scratch (allocation-free rule: __device__ globals)
__device__ __half g_h[(size_t)NN * F];     // 25.6 MB (fp16 intermediate)
__device__ float  g_agg[(size_t)NN * F];   // 51.2 MB
__device__ int    g_cnt[NN];               // zero-init; invariant: 0 at sequence end
__device__ int    g_rptr[NN + 1];
__device__ int    g_scol[NE];
__device__ int    g_part[SCAN_B];

// Host-side fork resources (created once at load; host objects only)
static cudaStream_t g_side;
static cudaEvent_t g_ev_fork, g_ev_join;
namespace {
struct HostInit {
  HostInit() {
    cudaStreamCreateWithFlags(&g_side, cudaStreamNonBlocking);
    cudaEventCreateWithFlags(&g_ev_fork, cudaEventDisableTiming);
    cudaEventCreateWithFlags(&g_ev_join, cudaEventDisableTiming);
  }
};
HostInit host_init_;
}

// ================= CSR build (4 kernels, self-cleaning counts) =================
__global__ void k_hist(const int* __restrict__ row) {
  int e = blockIdx.x * blockDim.x + threadIdx.x;
  if (e < NE) atomicAdd(&g_cnt[row[e]], 1);
}

// Block-local exclusive scan of counts -> rptr, block totals -> part
__global__ __launch_bounds__(SCAN_B) void k_scanA() {
  __shared__ int sh[SCAN_B];
  int g = blockIdx.x * SCAN_B + threadIdx.x;
  int v = (g < NN) ? g_cnt[g] : 0;
  sh[threadIdx.x] = v;
  __syncthreads();
#pragma unroll
  for (int off = 1; off < SCAN_B; off <<= 1) {
    int t = (threadIdx.x >= off) ? sh[threadIdx.x - off] : 0;
    __syncthreads();
    sh[threadIdx.x] += t;
    __syncthreads();
  }
  if (g < NN) g_rptr[g] = sh[threadIdx.x] - v;
  if (threadIdx.x == SCAN_B - 1) g_part[blockIdx.x] = sh[SCAN_B - 1];
}

// Fused: each block reduces the partials below it, adds offset, sets sentinel.
__global__ __launch_bounds__(SCAN_B) void k_scanBC() {
  __shared__ int red[SCAN_B];
  int b = blockIdx.x;
  red[threadIdx.x] = (threadIdx.x < b && threadIdx.x < NBLK) ? g_part[threadIdx.x] : 0;
  __syncthreads();
#pragma unroll
  for (int off = SCAN_B / 2; off > 0; off >>= 1) {
    if (threadIdx.x < off) red[threadIdx.x] += red[threadIdx.x + off];
    __syncthreads();
  }
  int offset = red[0];
  int g = b * SCAN_B + threadIdx.x;
  if (g < NN) g_rptr[g] += offset;
  if (g == 0) g_rptr[NN] = NE;
}

// Placement consumes counts down to zero (self-cleaning for next call).
__global__ void k_place(const int* __restrict__ row, const int* __restrict__ col) {
  int e = blockIdx.x * blockDim.x + threadIdx.x;
  if (e >= NE) return;
  int r = row[e];
  int pos = g_rptr[r] + atomicSub(&g_cnt[r], 1) - 1;
  g_scol[pos] = col[e];
}

// ================= fp16 mma.sync GEMM (single pass, 2 CTA/SM) =================
#define H_STRIDE 136                        // halves per row (128 + 8 pad)
#define TILE_HALVES (128 * H_STRIDE)        // 17408
#define GEMM_SMEM (2 * TILE_HALVES * 2)     // 69632 B

__device__ __forceinline__ void mma_f16(float* c, const uint32_t* a, const uint32_t* b) {
  asm volatile(
      "mma.sync.aligned.m16n8k16.row.col.f32.f16.f16.f32 "
      "{%0,%1,%2,%3}, {%4,%5,%6,%7}, {%8,%9}, {%0,%1,%2,%3};"
      : "+f"(c[0]), "+f"(c[1]), "+f"(c[2]), "+f"(c[3])
      : "r"(a[0]), "r"(a[1]), "r"(a[2]), "r"(a[3]), "r"(b[0]), "r"(b[1]));
}

__global__ __launch_bounds__(256, 2) void k_gemm_tc(
    const float* __restrict__ A, const float* __restrict__ W,
    const float* __restrict__ bias, __half* __restrict__ C, int M) {
  extern __shared__ __half sh[];
  __half* sA = sh;                 // [128][H_STRIDE]
  __half* sW = sh + TILE_HALVES;   // [128][H_STRIDE]

  const int tid = threadIdx.x;
  const int wid = tid >> 5;
  const int lane = tid & 31;
  const int wm = wid & 3;
  const int wn = wid >> 2;
  const int g = lane >> 2;
  const int t = lane & 3;
  const int m0 = blockIdx.x * 128;

#pragma unroll
  for (int it = 0; it < 16; it++) {
    int idx = it * 256 + tid;
    int row = idx >> 5;
    int cq = idx & 31;

    float4 va = make_float4(0.f, 0.f, 0.f, 0.f);
    if (m0 + row < M)
      va = *(const float4*)(A + (size_t)(m0 + row) * F + cq * 4);
    __half2 h0 = __floats2half2_rn(va.x, va.y);
    __half2 h1 = __floats2half2_rn(va.z, va.w);
    *(__half2*)&sA[row * H_STRIDE + cq * 4]     = h0;
    *(__half2*)&sA[row * H_STRIDE + cq * 4 + 2] = h1;

    float4 vw = *(const float4*)(W + (size_t)row * F + cq * 4);
    h0 = __floats2half2_rn(vw.x, vw.y);
    h1 = __floats2half2_rn(vw.z, vw.w);
    *(__half2*)&sW[row * H_STRIDE + cq * 4]     = h0;
    *(__half2*)&sW[row * H_STRIDE + cq * 4 + 2] = h1;
  }
  __syncthreads();

  float acc[2][8][4];
#pragma unroll
  for (int i = 0; i < 2; i++)
#pragma unroll
    for (int j = 0; j < 8; j++)
#pragma unroll
      for (int l = 0; l < 4; l++) acc[i][j][l] = 0.0f;

#pragma unroll
  for (int k16 = 0; k16 < 8; k16++) {
    const int kc = k16 * 16;
    uint32_t af[2][4];
#pragma unroll
    for (int mt = 0; mt < 2; mt++) {
      const __half* base = sA + (size_t)(wm * 32 + mt * 16 + g) * H_STRIDE + kc;
      af[mt][0] = *(const uint32_t*)(base + 2 * t);
      af[mt][1] = *(const uint32_t*)(base + 8 * H_STRIDE + 2 * t);
      af[mt][2] = *(const uint32_t*)(base + 2 * t + 8);
      af[mt][3] = *(const uint32_t*)(base + 8 * H_STRIDE + 2 * t + 8);
    }
#pragma unroll
    for (int nt = 0; nt < 8; nt++) {
      const __half* wbase = sW + (size_t)(wn * 64 + nt * 8 + g) * H_STRIDE + kc;
      uint32_t bf[2];
      bf[0] = *(const uint32_t*)(wbase + 2 * t);
      bf[1] = *(const uint32_t*)(wbase + 2 * t + 8);
#pragma unroll
      for (int mt = 0; mt < 2; mt++) mma_f16(acc[mt][nt], af[mt], bf);
    }
  }

#pragma unroll
  for (int mt = 0; mt < 2; mt++) {
    int row0 = m0 + wm * 32 + mt * 16 + g;
#pragma unroll
    for (int nt = 0; nt < 8; nt++) {
      int col = wn * 64 + nt * 8 + t * 2;
      float bx = __ldg(bias + col);
      float by = __ldg(bias + col + 1);
      if (row0 < M) {
        __half2 o = __floats2half2_rn(acc[mt][nt][0] + bx, acc[mt][nt][1] + by);
        *(__half2*)(C + (size_t)row0 * F + col) = o;
      }
      if (row0 + 8 < M) {
        __half2 o = __floats2half2_rn(acc[mt][nt][2] + bx, acc[mt][nt][3] + by);
        *(__half2*)(C + (size_t)(row0 + 8) * F + col) = o;
      }
    }
  }
}

// ================= CSR gather SpMM (fp16 src) + mean + optional ELU =================
__device__ __forceinline__ void acc_edge(float4& acc, const __half* src, int c, int lane) {
  uint2 v = ((const uint2*)(src + (size_t)c * F))[lane];
  float2 f0 = __half22float2(*(__half2*)&v.x);
  float2 f1 = __half22float2(*(__half2*)&v.y);
  acc.x += f0.x; acc.y += f0.y; acc.z += f1.x; acc.w += f1.y;
}

__global__ __launch_bounds__(256) void k_gather(
    const __half* __restrict__ src, float* __restrict__ dst, int apply_elu) {
  int node = blockIdx.x * 8 + (threadIdx.x >> 5);
  if (node >= NN) return;
  int lane = threadIdx.x & 31;

  int s = g_rptr[node];
  int e = g_rptr[node + 1];

  float4 acc = make_float4(0.f, 0.f, 0.f, 0.f);
  int j = s;
  for (; j + 4 <= e; j += 4) {
    int c0 = __ldg(&g_scol[j + 0]);
    int c1 = __ldg(&g_scol[j + 1]);
    int c2 = __ldg(&g_scol[j + 2]);
    int c3 = __ldg(&g_scol[j + 3]);
    acc_edge(acc, src, c0, lane);
    acc_edge(acc, src, c1, lane);
    acc_edge(acc, src, c2, lane);
    acc_edge(acc, src, c3, lane);
  }
  for (; j < e; j++) {
    int c = __ldg(&g_scol[j]);
    acc_edge(acc, src, c, lane);
  }

  float inv = (e > s) ? 1.0f / (float)(e - s) : 0.0f;
  acc.x *= inv; acc.y *= inv; acc.z *= inv; acc.w *= inv;
  if (apply_elu) {
    acc.x = acc.x > 0.f ? acc.x : expm1f(acc.x);
    acc.y = acc.y > 0.f ? acc.y : expm1f(acc.y);
    acc.z = acc.z > 0.f ? acc.z : expm1f(acc.z);
    acc.w = acc.w > 0.f ? acc.w : expm1f(acc.w);
  }
  ((float4*)(dst + (size_t)node * F))[lane] = acc;
}

extern "C" void kernel_launch(void* const* d_in, const int* in_sizes, int n_in,
                              void* d_out, int out_size) {
  const float* x  = (const float*)d_in[0];
  const int*   ei = (const int*)d_in[1];
  const float* W1 = (const float*)d_in[2];
  const float* b1 = (const float*)d_in[3];
  const float* W2 = (const float*)d_in[4];
  const float* b2 = (const float*)d_in[5];
  const int* row = ei;
  const int* col = ei + NE;
  float* out = (float*)d_out;

  void* p_h = nullptr;
  void* p_agg = nullptr;
  cudaGetSymbolAddress(&p_h, g_h);
  cudaGetSymbolAddress(&p_agg, g_agg);
  __half* h  = (__half*)p_h;
  float* agg = (float*)p_agg;

  cudaFuncSetAttribute(k_gemm_tc, cudaFuncAttributeMaxDynamicSharedMemorySize, GEMM_SMEM);

  const int gblocks = (NN + 127) / 128;   // 782

  // ---- fork: CSR build on side stream, GEMM1 on main stream ----
  cudaEventRecord(g_ev_fork, 0);
  cudaStreamWaitEvent(g_side, g_ev_fork, 0);

  k_hist<<<(NE + 511) / 512, 512, 0, g_side>>>(row);
  k_scanA<<<NBLK, SCAN_B, 0, g_side>>>();
  k_scanBC<<<NBLK, SCAN_B, 0, g_side>>>();
  k_place<<<(NE + 511) / 512, 512, 0, g_side>>>(row, col);
  cudaEventRecord(g_ev_join, g_side);

  k_gemm_tc<<<gblocks, 256, GEMM_SMEM>>>(x, W1, b1, h, NN);   // h = x W1^T + b1

  // ---- join, then the dependent chain ----
  cudaStreamWaitEvent(0, g_ev_join, 0);
  k_gather<<<(NN + 7) / 8, 256>>>(h, agg, 1);                 // agg = elu(mean-agg(h))
  k_gemm_tc<<<gblocks, 256, GEMM_SMEM>>>(agg, W2, b2, h, NN); // h = agg W2^T + b2
  k_gather<<<(NN + 7) / 8, 256>>>(h, out, 0);                 // out = mean-agg(h)
}

// round 9
// speedup vs baseline: 7.1892x; 1.0075x over previous
#include <cuda_runtime.h>
#include <cuda_fp16.h>
#include <math.h>
#include <stdint.h>

#define NN 100000
#define NE 1600000
#define F  128
#define SCAN_B 512
#define NBLK ((NN + SCAN_B - 1) / SCAN_B)   // 196

// Scratch (allocation-free rule: __device__ globals)
__device__ __half g_h[(size_t)NN * F];     // 25.6 MB (fp16 intermediate)
__device__ __half g_agg[(size_t)NN * F];   // 25.6 MB (fp16 intermediate)
__device__ int    g_cnt[NN];               // zero-init; invariant: 0 at sequence end
__device__ int    g_rptr[NN + 1];
__device__ int    g_scol[NE];
__device__ int    g_part[SCAN_B];

// Host-side fork resources (created once at load; host objects only)
static cudaStream_t g_side;
static cudaEvent_t g_ev_fork, g_ev_join;
namespace {
struct HostInit {
  HostInit() {
    cudaStreamCreateWithFlags(&g_side, cudaStreamNonBlocking);
    cudaEventCreateWithFlags(&g_ev_fork, cudaEventDisableTiming);
    cudaEventCreateWithFlags(&g_ev_join, cudaEventDisableTiming);
  }
};
HostInit host_init_;
}

// ================= CSR build (4 kernels, self-cleaning counts) =================
// 4 edges per thread (int4 load) -> 4 outstanding atomics (MLP=4).
__global__ void k_hist(const int* __restrict__ row) {
  int e = (blockIdx.x * blockDim.x + threadIdx.x) * 4;
  if (e + 3 < NE) {
    int4 r = *(const int4*)(row + e);
    atomicAdd(&g_cnt[r.x], 1);
    atomicAdd(&g_cnt[r.y], 1);
    atomicAdd(&g_cnt[r.z], 1);
    atomicAdd(&g_cnt[r.w], 1);
  } else {
    for (; e < NE; e++) atomicAdd(&g_cnt[row[e]], 1);
  }
}

// Block-local exclusive scan of counts -> rptr, block totals -> part
__global__ __launch_bounds__(SCAN_B) void k_scanA() {
  __shared__ int sh[SCAN_B];
  int g = blockIdx.x * SCAN_B + threadIdx.x;
  int v = (g < NN) ? g_cnt[g] : 0;
  sh[threadIdx.x] = v;
  __syncthreads();
#pragma unroll
  for (int off = 1; off < SCAN_B; off <<= 1) {
    int t = (threadIdx.x >= off) ? sh[threadIdx.x - off] : 0;
    __syncthreads();
    sh[threadIdx.x] += t;
    __syncthreads();
  }
  if (g < NN) g_rptr[g] = sh[threadIdx.x] - v;
  if (threadIdx.x == SCAN_B - 1) g_part[blockIdx.x] = sh[SCAN_B - 1];
}

// Fused: each block reduces the partials below it, adds offset, sets sentinel.
__global__ __launch_bounds__(SCAN_B) void k_scanBC() {
  __shared__ int red[SCAN_B];
  int b = blockIdx.x;
  red[threadIdx.x] = (threadIdx.x < b && threadIdx.x < NBLK) ? g_part[threadIdx.x] : 0;
  __syncthreads();
#pragma unroll
  for (int off = SCAN_B / 2; off > 0; off >>= 1) {
    if (threadIdx.x < off) red[threadIdx.x] += red[threadIdx.x + off];
    __syncthreads();
  }
  int offset = red[0];
  int g = b * SCAN_B + threadIdx.x;
  if (g < NN) g_rptr[g] += offset;
  if (g == 0) g_rptr[NN] = NE;
}

// Placement consumes counts down to zero (self-cleaning). 4 edges/thread.
__global__ void k_place(const int* __restrict__ row, const int* __restrict__ col) {
  int e = (blockIdx.x * blockDim.x + threadIdx.x) * 4;
  if (e + 3 < NE) {
    int4 r = *(const int4*)(row + e);
    int4 c = *(const int4*)(col + e);
    int p0 = atomicSub(&g_cnt[r.x], 1) - 1;
    int p1 = atomicSub(&g_cnt[r.y], 1) - 1;
    int p2 = atomicSub(&g_cnt[r.z], 1) - 1;
    int p3 = atomicSub(&g_cnt[r.w], 1) - 1;
    g_scol[g_rptr[r.x] + p0] = c.x;
    g_scol[g_rptr[r.y] + p1] = c.y;
    g_scol[g_rptr[r.z] + p2] = c.z;
    g_scol[g_rptr[r.w] + p3] = c.w;
  } else {
    for (; e < NE; e++) {
      int r = row[e];
      int pos = g_rptr[r] + atomicSub(&g_cnt[r], 1) - 1;
      g_scol[pos] = col[e];
    }
  }
}

// ================= fp16 mma.sync GEMM (single pass, 2 CTA/SM) =================
#define H_STRIDE 136                        // halves per row (128 + 8 pad)
#define TILE_HALVES (128 * H_STRIDE)        // 17408
#define GEMM_SMEM (2 * TILE_HALVES * 2)     // 69632 B

__device__ __forceinline__ void mma_f16(float* c, const uint32_t* a, const uint32_t* b) {
  asm volatile(
      "mma.sync.aligned.m16n8k16.row.col.f32.f16.f16.f32 "
      "{%0,%1,%2,%3}, {%4,%5,%6,%7}, {%8,%9}, {%0,%1,%2,%3};"
      : "+f"(c[0]), "+f"(c[1]), "+f"(c[2]), "+f"(c[3])
      : "r"(a[0]), "r"(a[1]), "r"(a[2]), "r"(a[3]), "r"(b[0]), "r"(b[1]));
}

// Shared mainloop + epilogue (A tile and W tile already in SMEM)
__device__ __forceinline__ void gemm_core(
    __half* sA, __half* sW, const float* __restrict__ bias,
    __half* __restrict__ C, int M, int m0, int tid) {
  const int wid = tid >> 5;
  const int lane = tid & 31;
  const int wm = wid & 3;
  const int wn = wid >> 2;
  const int g = lane >> 2;
  const int t = lane & 3;

  float acc[2][8][4];
#pragma unroll
  for (int i = 0; i < 2; i++)
#pragma unroll
    for (int j = 0; j < 8; j++)
#pragma unroll
      for (int l = 0; l < 4; l++) acc[i][j][l] = 0.0f;

#pragma unroll
  for (int k16 = 0; k16 < 8; k16++) {
    const int kc = k16 * 16;
    uint32_t af[2][4];
#pragma unroll
    for (int mt = 0; mt < 2; mt++) {
      const __half* base = sA + (size_t)(wm * 32 + mt * 16 + g) * H_STRIDE + kc;
      af[mt][0] = *(const uint32_t*)(base + 2 * t);
      af[mt][1] = *(const uint32_t*)(base + 8 * H_STRIDE + 2 * t);
      af[mt][2] = *(const uint32_t*)(base + 2 * t + 8);
      af[mt][3] = *(const uint32_t*)(base + 8 * H_STRIDE + 2 * t + 8);
    }
#pragma unroll
    for (int nt = 0; nt < 8; nt++) {
      const __half* wbase = sW + (size_t)(wn * 64 + nt * 8 + g) * H_STRIDE + kc;
      uint32_t bf[2];
      bf[0] = *(const uint32_t*)(wbase + 2 * t);
      bf[1] = *(const uint32_t*)(wbase + 2 * t + 8);
#pragma unroll
      for (int mt = 0; mt < 2; mt++) mma_f16(acc[mt][nt], af[mt], bf);
    }
  }

#pragma unroll
  for (int mt = 0; mt < 2; mt++) {
    int row0 = m0 + wm * 32 + mt * 16 + g;
#pragma unroll
    for (int nt = 0; nt < 8; nt++) {
      int col = wn * 64 + nt * 8 + t * 2;
      float bx = __ldg(bias + col);
      float by = __ldg(bias + col + 1);
      if (row0 < M) {
        __half2 o = __floats2half2_rn(acc[mt][nt][0] + bx, acc[mt][nt][1] + by);
        *(__half2*)(C + (size_t)row0 * F + col) = o;
      }
      if (row0 + 8 < M) {
        __half2 o = __floats2half2_rn(acc[mt][nt][2] + bx, acc[mt][nt][3] + by);
        *(__half2*)(C + (size_t)(row0 + 8) * F + col) = o;
      }
    }
  }
}

// A in fp32 (layer 1)
__global__ __launch_bounds__(256, 2) void k_gemm_tc(
    const float* __restrict__ A, const float* __restrict__ W,
    const float* __restrict__ bias, __half* __restrict__ C, int M) {
  extern __shared__ __half sh[];
  __half* sA = sh;
  __half* sW = sh + TILE_HALVES;
  const int tid = threadIdx.x;
  const int m0 = blockIdx.x * 128;

#pragma unroll
  for (int it = 0; it < 16; it++) {
    int idx = it * 256 + tid;
    int row = idx >> 5;
    int cq = idx & 31;

    float4 va = make_float4(0.f, 0.f, 0.f, 0.f);
    if (m0 + row < M)
      va = *(const float4*)(A + (size_t)(m0 + row) * F + cq * 4);
    *(__half2*)&sA[row * H_STRIDE + cq * 4]     = __floats2half2_rn(va.x, va.y);
    *(__half2*)&sA[row * H_STRIDE + cq * 4 + 2] = __floats2half2_rn(va.z, va.w);

    float4 vw = *(const float4*)(W + (size_t)row * F + cq * 4);
    *(__half2*)&sW[row * H_STRIDE + cq * 4]     = __floats2half2_rn(vw.x, vw.y);
    *(__half2*)&sW[row * H_STRIDE + cq * 4 + 2] = __floats2half2_rn(vw.z, vw.w);
  }
  __syncthreads();
  gemm_core(sA, sW, bias, C, M, m0, tid);
}

// A in fp16 (layer 2): raw uint4 copies, no conversion
__global__ __launch_bounds__(256, 2) void k_gemm_tc_h(
    const __half* __restrict__ A, const float* __restrict__ W,
    const float* __restrict__ bias, __half* __restrict__ C, int M) {
  extern __shared__ __half sh[];
  __half* sA = sh;
  __half* sW = sh + TILE_HALVES;
  const int tid = threadIdx.x;
  const int m0 = blockIdx.x * 128;

  // A: 128 rows x 16 uint4-chunks (8 halves each) = 2048; 8 per thread
#pragma unroll
  for (int it = 0; it < 8; it++) {
    int idx = it * 256 + tid;
    int row = idx >> 4;
    int c8 = idx & 15;
    uint4 v = make_uint4(0, 0, 0, 0);
    if (m0 + row < M)
      v = *(const uint4*)(A + (size_t)(m0 + row) * F + c8 * 8);
    *(uint4*)&sA[row * H_STRIDE + c8 * 8] = v;
  }
  // W: fp32 -> fp16 convert (16 float4-chunks per row)
#pragma unroll
  for (int it = 0; it < 16; it++) {
    int idx = it * 256 + tid;
    int row = idx >> 5;
    int cq = idx & 31;
    float4 vw = *(const float4*)(W + (size_t)row * F + cq * 4);
    *(__half2*)&sW[row * H_STRIDE + cq * 4]     = __floats2half2_rn(vw.x, vw.y);
    *(__half2*)&sW[row * H_STRIDE + cq * 4 + 2] = __floats2half2_rn(vw.z, vw.w);
  }
  __syncthreads();
  gemm_core(sA, sW, bias, C, M, m0, tid);
}

// ================= CSR gather SpMM (fp16 src) + mean =================
// MODE 0: ELU + fp16 out (layer 1). MODE 1: no ELU + fp32 out (layer 2).
__device__ __forceinline__ void acc_edge(float4& acc, const __half* src, int c, int lane) {
  uint2 v = ((const uint2*)(src + (size_t)c * F))[lane];
  float2 f0 = __half22float2(*(__half2*)&v.x);
  float2 f1 = __half22float2(*(__half2*)&v.y);
  acc.x += f0.x; acc.y += f0.y; acc.z += f1.x; acc.w += f1.y;
}

template <int MODE>
__global__ __launch_bounds__(256) void k_gather(
    const __half* __restrict__ src, void* __restrict__ dst_) {
  int node = blockIdx.x * 8 + (threadIdx.x >> 5);
  if (node >= NN) return;
  int lane = threadIdx.x & 31;

  int s = g_rptr[node];
  int e = g_rptr[node + 1];

  float4 acc = make_float4(0.f, 0.f, 0.f, 0.f);
  int j = s;
  for (; j + 4 <= e; j += 4) {
    int c0 = __ldg(&g_scol[j + 0]);
    int c1 = __ldg(&g_scol[j + 1]);
    int c2 = __ldg(&g_scol[j + 2]);
    int c3 = __ldg(&g_scol[j + 3]);
    acc_edge(acc, src, c0, lane);
    acc_edge(acc, src, c1, lane);
    acc_edge(acc, src, c2, lane);
    acc_edge(acc, src, c3, lane);
  }
  for (; j < e; j++) {
    int c = __ldg(&g_scol[j]);
    acc_edge(acc, src, c, lane);
  }

  float inv = (e > s) ? 1.0f / (float)(e - s) : 0.0f;
  acc.x *= inv; acc.y *= inv; acc.z *= inv; acc.w *= inv;
  if (MODE == 0) {
    acc.x = acc.x > 0.f ? acc.x : expm1f(acc.x);
    acc.y = acc.y > 0.f ? acc.y : expm1f(acc.y);
    acc.z = acc.z > 0.f ? acc.z : expm1f(acc.z);
    acc.w = acc.w > 0.f ? acc.w : expm1f(acc.w);
    __half* dst = (__half*)dst_;
    uint2 o;
    *(__half2*)&o.x = __floats2half2_rn(acc.x, acc.y);
    *(__half2*)&o.y = __floats2half2_rn(acc.z, acc.w);
    ((uint2*)(dst + (size_t)node * F))[lane] = o;
  } else {
    float* dst = (float*)dst_;
    ((float4*)(dst + (size_t)node * F))[lane] = acc;
  }
}

extern "C" void kernel_launch(void* const* d_in, const int* in_sizes, int n_in,
                              void* d_out, int out_size) {
  const float* x  = (const float*)d_in[0];
  const int*   ei = (const int*)d_in[1];
  const float* W1 = (const float*)d_in[2];
  const float* b1 = (const float*)d_in[3];
  const float* W2 = (const float*)d_in[4];
  const float* b2 = (const float*)d_in[5];
  const int* row = ei;
  const int* col = ei + NE;
  float* out = (float*)d_out;

  void* p_h = nullptr;
  void* p_agg = nullptr;
  cudaGetSymbolAddress(&p_h, g_h);
  cudaGetSymbolAddress(&p_agg, g_agg);
  __half* h   = (__half*)p_h;
  __half* agg = (__half*)p_agg;

  cudaFuncSetAttribute(k_gemm_tc, cudaFuncAttributeMaxDynamicSharedMemorySize, GEMM_SMEM);
  cudaFuncSetAttribute(k_gemm_tc_h, cudaFuncAttributeMaxDynamicSharedMemorySize, GEMM_SMEM);

  const int gblocks = (NN + 127) / 128;    // 782
  const int eblocks4 = (NE / 4 + 511) / 512; // 782

  // ---- fork: CSR build on side stream, GEMM1 on main stream ----
  cudaEventRecord(g_ev_fork, 0);
  cudaStreamWaitEvent(g_side, g_ev_fork, 0);

  k_hist<<<eblocks4, 512, 0, g_side>>>(row);
  k_scanA<<<NBLK, SCAN_B, 0, g_side>>>();
  k_scanBC<<<NBLK, SCAN_B, 0, g_side>>>();
  k_place<<<eblocks4, 512, 0, g_side>>>(row, col);
  cudaEventRecord(g_ev_join, g_side);

  k_gemm_tc<<<gblocks, 256, GEMM_SMEM>>>(x, W1, b1, h, NN);     // h = x W1^T + b1

  // ---- join, then the dependent chain ----
  cudaStreamWaitEvent(0, g_ev_join, 0);
  k_gather<0><<<(NN + 7) / 8, 256>>>(h, agg);                   // agg = elu(mean-agg(h)) [fp16]
  k_gemm_tc_h<<<gblocks, 256, GEMM_SMEM>>>(agg, W2, b2, h, NN); // h = agg W2^T + b2
  k_gather<1><<<(NN + 7) / 8, 256>>>(h, out);                   // out = mean-agg(h) [fp32]
}